// round 1
// baseline (speedup 1.0000x reference)
#include <cuda_runtime.h>

#define BB 4
#define LQ 256
#define LK 256
#define DD 768

// Scratch (no cudaMalloc allowed)
__device__ float g_q[BB*LQ*DD];
__device__ float g_k[BB*LK*DD];
__device__ float g_v[BB*LK*DD];
__device__ float g_scores[BB*LQ*LK];

__device__ __forceinline__ float tanh_fast(float x) {
    float y;
    asm("tanh.approx.f32 %0, %1;" : "=f"(y) : "f"(x));
    return y;
}

// ---------------------------------------------------------------------------
// Projection GEMM: Out[M,N] = X[M,K] @ W[K,N] + b[N].  M=1024, N=K=768.
// blockIdx.z selects which of the 3 projections. 128x128 tile, BK=8, 8x8 micro.
// ---------------------------------------------------------------------------
__global__ __launch_bounds__(256) void proj_kernel(
    const float* __restrict__ xq, const float* __restrict__ xk, const float* __restrict__ xv,
    const float* __restrict__ Wq, const float* __restrict__ bq,
    const float* __restrict__ Wk, const float* __restrict__ bk,
    const float* __restrict__ Wv, const float* __restrict__ bv)
{
    const int N = DD, K = DD;
    const float *X, *W, *bias;
    float* Out;
    if (blockIdx.z == 0)      { X = xq; W = Wq; bias = bq; Out = g_q; }
    else if (blockIdx.z == 1) { X = xk; W = Wk; bias = bk; Out = g_k; }
    else                      { X = xv; W = Wv; bias = bv; Out = g_v; }

    __shared__ float As[8][128];   // A transposed: As[k][m]
    __shared__ float Bs[8][128];   // Bs[k][n]

    const int t  = threadIdx.x;
    const int tx = t & 15, ty = t >> 4;
    const int m0 = blockIdx.y * 128;
    const int n0 = blockIdx.x * 128;

    float acc[8][8];
    #pragma unroll
    for (int i = 0; i < 8; i++)
        #pragma unroll
        for (int j = 0; j < 8; j++) acc[i][j] = 0.f;

    const int lr = t >> 1, lc = (t & 1) * 4;     // A-tile load: 128 rows x 8 cols
    const int wr = t >> 5, wc = (t & 31) * 4;    // B-tile load: 8 rows x 128 cols

    const float* Xp = X + (m0 + lr) * K + lc;
    const float* Wp = W + wr * N + n0 + wc;

    for (int k0 = 0; k0 < K; k0 += 8) {
        float4 a4 = *(const float4*)(Xp + k0);
        float4 b4 = *(const float4*)(Wp + (size_t)k0 * N);
        As[lc+0][lr] = a4.x; As[lc+1][lr] = a4.y;
        As[lc+2][lr] = a4.z; As[lc+3][lr] = a4.w;
        *(float4*)&Bs[wr][wc] = b4;
        __syncthreads();
        #pragma unroll
        for (int kk = 0; kk < 8; kk++) {
            float a[8], b[8];
            *(float4*)&a[0] = *(const float4*)&As[kk][ty*8];
            *(float4*)&a[4] = *(const float4*)&As[kk][ty*8+4];
            *(float4*)&b[0] = *(const float4*)&Bs[kk][tx*8];
            *(float4*)&b[4] = *(const float4*)&Bs[kk][tx*8+4];
            #pragma unroll
            for (int i = 0; i < 8; i++)
                #pragma unroll
                for (int j = 0; j < 8; j++)
                    acc[i][j] = fmaf(a[i], b[j], acc[i][j]);
        }
        __syncthreads();
    }

    #pragma unroll
    for (int i = 0; i < 8; i++) {
        const int m = m0 + ty*8 + i;
        #pragma unroll
        for (int j = 0; j < 8; j += 4) {
            const int n = n0 + tx*8 + j;
            float4 r;
            r.x = acc[i][j+0] + bias[n+0];
            r.y = acc[i][j+1] + bias[n+1];
            r.z = acc[i][j+2] + bias[n+2];
            r.w = acc[i][j+3] + bias[n+3];
            *(float4*)&Out[(size_t)m * N + n] = r;
        }
    }
}

// ---------------------------------------------------------------------------
// Scores: s[b,i,j] = sum_d Ws[d]*tanh(q[b,i,d]+k[b,j,d]) + bs
// 32x32 (q,k) tile per block, D chunked by 64 through smem, 2x2 microtile.
// MUFU(tanh)-bound by design.
// ---------------------------------------------------------------------------
__global__ __launch_bounds__(256) void score_kernel(const float* __restrict__ Ws,
                                                    const float* __restrict__ bsp)
{
    const int bz = blockIdx.z;
    const int q0 = blockIdx.y * 32;
    const int k0 = blockIdx.x * 32;

    __shared__ float Qs[32][65];   // pad 65: Ks[tx*2][d] stride 130 -> conflict-free
    __shared__ float Ks[32][65];
    __shared__ float Wss[64];

    const int t  = threadIdx.x;
    const int tx = t & 15, ty = t >> 4;

    float acc00 = 0.f, acc01 = 0.f, acc10 = 0.f, acc11 = 0.f;

    const float* qb = g_q + ((size_t)bz*LQ + q0) * DD;
    const float* kb = g_k + ((size_t)bz*LK + k0) * DD;

    const int lrow = t >> 3;            // 0..31
    const int lcol = (t & 7) * 8;       // 0..56

    for (int d0 = 0; d0 < DD; d0 += 64) {
        float4 x0 = *(const float4*)&qb[(size_t)lrow*DD + d0 + lcol];
        float4 x1 = *(const float4*)&qb[(size_t)lrow*DD + d0 + lcol + 4];
        Qs[lrow][lcol+0] = x0.x; Qs[lrow][lcol+1] = x0.y;
        Qs[lrow][lcol+2] = x0.z; Qs[lrow][lcol+3] = x0.w;
        Qs[lrow][lcol+4] = x1.x; Qs[lrow][lcol+5] = x1.y;
        Qs[lrow][lcol+6] = x1.z; Qs[lrow][lcol+7] = x1.w;
        float4 y0 = *(const float4*)&kb[(size_t)lrow*DD + d0 + lcol];
        float4 y1 = *(const float4*)&kb[(size_t)lrow*DD + d0 + lcol + 4];
        Ks[lrow][lcol+0] = y0.x; Ks[lrow][lcol+1] = y0.y;
        Ks[lrow][lcol+2] = y0.z; Ks[lrow][lcol+3] = y0.w;
        Ks[lrow][lcol+4] = y1.x; Ks[lrow][lcol+5] = y1.y;
        Ks[lrow][lcol+6] = y1.z; Ks[lrow][lcol+7] = y1.w;
        if (t < 16) *(float4*)&Wss[t*4] = *(const float4*)&Ws[d0 + t*4];
        __syncthreads();

        #pragma unroll 16
        for (int d = 0; d < 64; d++) {
            const float w  = Wss[d];
            const float qa = Qs[ty*2+0][d];
            const float qc = Qs[ty*2+1][d];
            const float ka = Ks[tx*2+0][d];
            const float kc = Ks[tx*2+1][d];
            acc00 = fmaf(w, tanh_fast(qa + ka), acc00);
            acc01 = fmaf(w, tanh_fast(qa + kc), acc01);
            acc10 = fmaf(w, tanh_fast(qc + ka), acc10);
            acc11 = fmaf(w, tanh_fast(qc + kc), acc11);
        }
        __syncthreads();
    }

    const float bsv = *bsp;
    float* sp = g_scores + ((size_t)bz*LQ + q0) * LK + k0;
    sp[(ty*2+0)*LK + tx*2+0] = acc00 + bsv;
    sp[(ty*2+0)*LK + tx*2+1] = acc01 + bsv;
    sp[(ty*2+1)*LK + tx*2+0] = acc10 + bsv;
    sp[(ty*2+1)*LK + tx*2+1] = acc11 + bsv;
}

// ---------------------------------------------------------------------------
// Row softmax over LK=256. One block (256 threads) per (b,q) row.
// Writes attention_weights into d_out's second region.
// ---------------------------------------------------------------------------
__global__ __launch_bounds__(256) void softmax_kernel(float* __restrict__ wout)
{
    const int row = blockIdx.x;      // 0..B*LQ-1
    const int t   = threadIdx.x;     // 0..255
    __shared__ float red[8];

    const float v = g_scores[(size_t)row*LK + t];

    float m = v;
    #pragma unroll
    for (int o = 16; o > 0; o >>= 1) m = fmaxf(m, __shfl_xor_sync(0xffffffffu, m, o));
    if ((t & 31) == 0) red[t >> 5] = m;
    __syncthreads();
    float mx = red[0];
    #pragma unroll
    for (int i = 1; i < 8; i++) mx = fmaxf(mx, red[i]);
    __syncthreads();

    const float e = __expf(v - mx);
    float s = e;
    #pragma unroll
    for (int o = 16; o > 0; o >>= 1) s += __shfl_xor_sync(0xffffffffu, s, o);
    if ((t & 31) == 0) red[t >> 5] = s;
    __syncthreads();
    float sum = 0.f;
    #pragma unroll
    for (int i = 0; i < 8; i++) sum += red[i];

    wout[(size_t)row*LK + t] = e * (1.0f / sum);
}

// ---------------------------------------------------------------------------
// attended[b,i,:] = sum_j w[b,i,j] * v[b,j,:]
// Block: 32 q-rows x 128 d-cols, K(j) chunked by 32 through smem. 2x8 micro.
// ---------------------------------------------------------------------------
__global__ __launch_bounds__(256) void av_kernel(const float* __restrict__ wts,
                                                 float* __restrict__ out)
{
    const int bz = blockIdx.z;
    const int q0 = blockIdx.y * 32;
    const int d0 = blockIdx.x * 128;

    __shared__ float Vs[32][128];
    __shared__ float Wsm[32][33];

    const int t  = threadIdx.x;
    const int tx = t & 15, ty = t >> 4;

    float acc[2][8];
    #pragma unroll
    for (int i = 0; i < 2; i++)
        #pragma unroll
        for (int j = 0; j < 8; j++) acc[i][j] = 0.f;

    const int vr = t >> 3, vc = (t & 7) * 16;     // V: 32 rows x 128 cols
    const int qr = t >> 3, jc = (t & 7) * 4;      // W: 32 rows x 32 cols

    for (int j0 = 0; j0 < LK; j0 += 32) {
        const float* vp = g_v + ((size_t)bz*LK + j0 + vr) * DD + d0 + vc;
        #pragma unroll
        for (int u = 0; u < 4; u++)
            *(float4*)&Vs[vr][vc + u*4] = *(const float4*)(vp + u*4);
        float4 w4 = *(const float4*)&wts[((size_t)bz*LQ + q0 + qr) * LK + j0 + jc];
        Wsm[qr][jc+0] = w4.x; Wsm[qr][jc+1] = w4.y;
        Wsm[qr][jc+2] = w4.z; Wsm[qr][jc+3] = w4.w;
        __syncthreads();

        #pragma unroll
        for (int j = 0; j < 32; j++) {
            const float w0 = Wsm[ty*2+0][j];
            const float w1 = Wsm[ty*2+1][j];
            float4 v0 = *(const float4*)&Vs[j][tx*8];
            float4 v1 = *(const float4*)&Vs[j][tx*8+4];
            acc[0][0] = fmaf(w0, v0.x, acc[0][0]);
            acc[0][1] = fmaf(w0, v0.y, acc[0][1]);
            acc[0][2] = fmaf(w0, v0.z, acc[0][2]);
            acc[0][3] = fmaf(w0, v0.w, acc[0][3]);
            acc[0][4] = fmaf(w0, v1.x, acc[0][4]);
            acc[0][5] = fmaf(w0, v1.y, acc[0][5]);
            acc[0][6] = fmaf(w0, v1.z, acc[0][6]);
            acc[0][7] = fmaf(w0, v1.w, acc[0][7]);
            acc[1][0] = fmaf(w1, v0.x, acc[1][0]);
            acc[1][1] = fmaf(w1, v0.y, acc[1][1]);
            acc[1][2] = fmaf(w1, v0.z, acc[1][2]);
            acc[1][3] = fmaf(w1, v0.w, acc[1][3]);
            acc[1][4] = fmaf(w1, v1.x, acc[1][4]);
            acc[1][5] = fmaf(w1, v1.y, acc[1][5]);
            acc[1][6] = fmaf(w1, v1.z, acc[1][6]);
            acc[1][7] = fmaf(w1, v1.w, acc[1][7]);
        }
        __syncthreads();
    }

    #pragma unroll
    for (int i = 0; i < 2; i++) {
        float* op = out + ((size_t)bz*LQ + q0 + ty*2 + i) * DD + d0 + tx*8;
        float4 r0 = { acc[i][0], acc[i][1], acc[i][2], acc[i][3] };
        float4 r1 = { acc[i][4], acc[i][5], acc[i][6], acc[i][7] };
        *(float4*)(op + 0) = r0;
        *(float4*)(op + 4) = r1;
    }
}

// ---------------------------------------------------------------------------
extern "C" void kernel_launch(void* const* d_in, const int* in_sizes, int n_in,
                              void* d_out, int out_size)
{
    const float* query = (const float*)d_in[0];
    const float* key   = (const float*)d_in[1];
    const float* value = (const float*)d_in[2];
    const float* Wq    = (const float*)d_in[3];
    const float* bq    = (const float*)d_in[4];
    const float* Wk    = (const float*)d_in[5];
    const float* bk    = (const float*)d_in[6];
    const float* Wv    = (const float*)d_in[7];
    const float* bv    = (const float*)d_in[8];
    const float* Ws    = (const float*)d_in[9];
    const float* bs    = (const float*)d_in[10];

    float* att = (float*)d_out;                  // [B,LQ,D]
    float* wts = att + (size_t)BB * LQ * DD;     // [B,LQ,LK]

    // 1) q/k/v projections: one fused-grid GEMM (z selects projection)
    proj_kernel<<<dim3(DD/128, (BB*LQ)/128, 3), 256>>>(
        query, key, value, Wq, bq, Wk, bk, Wv, bv);

    // 2) additive scores (tanh-bound)
    score_kernel<<<dim3(LK/32, LQ/32, BB), 256>>>(Ws, bs);

    // 3) softmax -> attention_weights directly into d_out
    softmax_kernel<<<BB*LQ, 256>>>(wts);

    // 4) attended = weights @ v
    av_kernel<<<dim3(DD/128, LQ/32, BB), 256>>>(wts, att);
}

// round 3
// speedup vs baseline: 1.0481x; 1.0481x over previous
#include <cuda_runtime.h>

#define BB 4
#define LQ 256
#define LK 256
#define DD 768

// Scratch (no cudaMalloc allowed)
__device__ float g_q[BB*LQ*DD];
__device__ float g_k[BB*LK*DD];
__device__ float g_v[BB*LK*DD];
__device__ float g_scores[BB*LQ*LK];

__device__ __forceinline__ float tanh_fast(float x) {
    float y;
    asm("tanh.approx.f32 %0, %1;" : "=f"(y) : "f"(x));
    return y;
}

// ---- packed fp32x2 helpers (Blackwell FFMA2 path) ----
__device__ __forceinline__ unsigned long long pack2(float lo, float hi) {
    unsigned long long r;
    asm("mov.b64 %0, {%1, %2};" : "=l"(r) : "f"(lo), "f"(hi));
    return r;
}
__device__ __forceinline__ void ffma2(unsigned long long& acc,
                                      unsigned long long a,
                                      unsigned long long b) {
    asm("fma.rn.f32x2 %0, %1, %2, %0;" : "+l"(acc) : "l"(a), "l"(b));
}
__device__ __forceinline__ float2 unpack2(unsigned long long v) {
    float lo, hi;
    asm("mov.b64 {%0, %1}, %2;" : "=f"(lo), "=f"(hi) : "l"(v));
    return make_float2(lo, hi);
}

// ---------------------------------------------------------------------------
// Projection GEMM: Out[M,N] = X[M,K] @ W[K,N] + b[N].  M=1024, N=K=768.
// 128x128 tile, BK=16, double-buffered smem, 8x8 micro via FFMA2 (f32x2).
// blockIdx.z selects projection.
// ---------------------------------------------------------------------------
__global__ __launch_bounds__(256) void proj_kernel(
    const float* __restrict__ xq, const float* __restrict__ xk, const float* __restrict__ xv,
    const float* __restrict__ Wq, const float* __restrict__ bq,
    const float* __restrict__ Wk, const float* __restrict__ bk,
    const float* __restrict__ Wv, const float* __restrict__ bv)
{
    const int N = DD, K = DD;
    const float *X, *W, *bias;
    float* Out;
    if (blockIdx.z == 0)      { X = xq; W = Wq; bias = bq; Out = g_q; }
    else if (blockIdx.z == 1) { X = xk; W = Wk; bias = bk; Out = g_k; }
    else                      { X = xv; W = Wv; bias = bv; Out = g_v; }

    __shared__ float As[2][16][128];   // A transposed: As[k][m]
    __shared__ float Bs[2][16][128];   // Bs[k][n]

    const int t  = threadIdx.x;
    const int tx = t & 15, ty = t >> 4;
    const int m0 = blockIdx.y * 128;
    const int n0 = blockIdx.x * 128;

    // accumulators: 8 rows x 4 n-pairs (f32x2)
    unsigned long long acc[8][4];
    #pragma unroll
    for (int i = 0; i < 8; i++)
        #pragma unroll
        for (int p = 0; p < 4; p++) acc[i][p] = 0ull;

    // A tile load: 128 rows x 16 cols, each thread 2 float4 (row lr, cols lc..lc+7)
    const int lr = t >> 1, lc = (t & 1) * 8;
    // B tile load: 16 rows x 128 cols, each thread 2 float4
    const int wr = t >> 4, wc = (t & 15) * 8;

    const float* Xp = X + (size_t)(m0 + lr) * K + lc;
    const float* Wp = W + (size_t)wr * N + n0 + wc;

    // prefetch tile 0
    float4 pa0 = *(const float4*)(Xp + 0);
    float4 pa1 = *(const float4*)(Xp + 4);
    float4 pb0 = *(const float4*)(Wp + 0);
    float4 pb1 = *(const float4*)(Wp + 4);

    int buf = 0;
    for (int k0 = 0; k0 < K; k0 += 16) {
        // store prefetched tile
        As[buf][lc+0][lr] = pa0.x; As[buf][lc+1][lr] = pa0.y;
        As[buf][lc+2][lr] = pa0.z; As[buf][lc+3][lr] = pa0.w;
        As[buf][lc+4][lr] = pa1.x; As[buf][lc+5][lr] = pa1.y;
        As[buf][lc+6][lr] = pa1.z; As[buf][lc+7][lr] = pa1.w;
        *(float4*)&Bs[buf][wr][wc]     = pb0;
        *(float4*)&Bs[buf][wr][wc + 4] = pb1;
        __syncthreads();

        // prefetch next tile while computing this one
        if (k0 + 16 < K) {
            pa0 = *(const float4*)(Xp + k0 + 16);
            pa1 = *(const float4*)(Xp + k0 + 20);
            pb0 = *(const float4*)(Wp + (size_t)(k0 + 16) * N);
            pb1 = *(const float4*)(Wp + (size_t)(k0 + 16) * N + 4);
        }

        #pragma unroll
        for (int kk = 0; kk < 16; kk++) {
            float a[8];
            *(float4*)&a[0] = *(const float4*)&As[buf][kk][ty*8];
            *(float4*)&a[4] = *(const float4*)&As[buf][kk][ty*8 + 4];
            ulonglong2 b01 = *(const ulonglong2*)&Bs[buf][kk][tx*8];
            ulonglong2 b23 = *(const ulonglong2*)&Bs[buf][kk][tx*8 + 4];
            unsigned long long bb[4] = { b01.x, b01.y, b23.x, b23.y };
            #pragma unroll
            for (int i = 0; i < 8; i++) {
                unsigned long long aa = pack2(a[i], a[i]);
                #pragma unroll
                for (int p = 0; p < 4; p++) ffma2(acc[i][p], aa, bb[p]);
            }
        }
        __syncthreads();
        buf ^= 1;
    }

    #pragma unroll
    for (int i = 0; i < 8; i++) {
        const int m = m0 + ty*8 + i;
        const int n = n0 + tx*8;
        float4 r0, r1;
        float2 p0 = unpack2(acc[i][0]);
        float2 p1 = unpack2(acc[i][1]);
        float2 p2 = unpack2(acc[i][2]);
        float2 p3 = unpack2(acc[i][3]);
        r0.x = p0.x + bias[n+0]; r0.y = p0.y + bias[n+1];
        r0.z = p1.x + bias[n+2]; r0.w = p1.y + bias[n+3];
        r1.x = p2.x + bias[n+4]; r1.y = p2.y + bias[n+5];
        r1.z = p3.x + bias[n+6]; r1.w = p3.y + bias[n+7];
        *(float4*)&Out[(size_t)m * N + n]     = r0;
        *(float4*)&Out[(size_t)m * N + n + 4] = r1;
    }
}

// ---------------------------------------------------------------------------
// Scores: s[b,i,j] = sum_d Ws[d]*tanh(q[b,i,d]+k[b,j,d]) + bs
// 32x32 (q,k) tile per block, D chunked by 64 through smem, 2x2 microtile.
// MUFU(tanh)-bound by design.
// ---------------------------------------------------------------------------
__global__ __launch_bounds__(256) void score_kernel(const float* __restrict__ Ws,
                                                    const float* __restrict__ bsp)
{
    const int bz = blockIdx.z;
    const int q0 = blockIdx.y * 32;
    const int k0 = blockIdx.x * 32;

    __shared__ float Qs[32][65];
    __shared__ float Ks[32][65];
    __shared__ float Wss[64];

    const int t  = threadIdx.x;
    const int tx = t & 15, ty = t >> 4;

    float acc00 = 0.f, acc01 = 0.f, acc10 = 0.f, acc11 = 0.f;

    const float* qb = g_q + ((size_t)bz*LQ + q0) * DD;
    const float* kb = g_k + ((size_t)bz*LK + k0) * DD;

    const int lrow = t >> 3;
    const int lcol = (t & 7) * 8;

    for (int d0 = 0; d0 < DD; d0 += 64) {
        float4 x0 = *(const float4*)&qb[(size_t)lrow*DD + d0 + lcol];
        float4 x1 = *(const float4*)&qb[(size_t)lrow*DD + d0 + lcol + 4];
        Qs[lrow][lcol+0] = x0.x; Qs[lrow][lcol+1] = x0.y;
        Qs[lrow][lcol+2] = x0.z; Qs[lrow][lcol+3] = x0.w;
        Qs[lrow][lcol+4] = x1.x; Qs[lrow][lcol+5] = x1.y;
        Qs[lrow][lcol+6] = x1.z; Qs[lrow][lcol+7] = x1.w;
        float4 y0 = *(const float4*)&kb[(size_t)lrow*DD + d0 + lcol];
        float4 y1 = *(const float4*)&kb[(size_t)lrow*DD + d0 + lcol + 4];
        Ks[lrow][lcol+0] = y0.x; Ks[lrow][lcol+1] = y0.y;
        Ks[lrow][lcol+2] = y0.z; Ks[lrow][lcol+3] = y0.w;
        Ks[lrow][lcol+4] = y1.x; Ks[lrow][lcol+5] = y1.y;
        Ks[lrow][lcol+6] = y1.z; Ks[lrow][lcol+7] = y1.w;
        if (t < 16) *(float4*)&Wss[t*4] = *(const float4*)&Ws[d0 + t*4];
        __syncthreads();

        #pragma unroll 16
        for (int d = 0; d < 64; d++) {
            const float w  = Wss[d];
            const float qa = Qs[ty*2+0][d];
            const float qc = Qs[ty*2+1][d];
            const float ka = Ks[tx*2+0][d];
            const float kc = Ks[tx*2+1][d];
            acc00 = fmaf(w, tanh_fast(qa + ka), acc00);
            acc01 = fmaf(w, tanh_fast(qa + kc), acc01);
            acc10 = fmaf(w, tanh_fast(qc + ka), acc10);
            acc11 = fmaf(w, tanh_fast(qc + kc), acc11);
        }
        __syncthreads();
    }

    const float bsv = *bsp;
    float* sp = g_scores + ((size_t)bz*LQ + q0) * LK + k0;
    sp[(ty*2+0)*LK + tx*2+0] = acc00 + bsv;
    sp[(ty*2+0)*LK + tx*2+1] = acc01 + bsv;
    sp[(ty*2+1)*LK + tx*2+0] = acc10 + bsv;
    sp[(ty*2+1)*LK + tx*2+1] = acc11 + bsv;
}

// ---------------------------------------------------------------------------
// Row softmax over LK=256. One block (256 threads) per (b,q) row.
// ---------------------------------------------------------------------------
__global__ __launch_bounds__(256) void softmax_kernel(float* __restrict__ wout)
{
    const int row = blockIdx.x;
    const int t   = threadIdx.x;
    __shared__ float red[8];

    const float v = g_scores[(size_t)row*LK + t];

    float m = v;
    #pragma unroll
    for (int o = 16; o > 0; o >>= 1) m = fmaxf(m, __shfl_xor_sync(0xffffffffu, m, o));
    if ((t & 31) == 0) red[t >> 5] = m;
    __syncthreads();
    float mx = red[0];
    #pragma unroll
    for (int i = 1; i < 8; i++) mx = fmaxf(mx, red[i]);
    __syncthreads();

    const float e = __expf(v - mx);
    float s = e;
    #pragma unroll
    for (int o = 16; o > 0; o >>= 1) s += __shfl_xor_sync(0xffffffffu, s, o);
    if ((t & 31) == 0) red[t >> 5] = s;
    __syncthreads();
    float sum = 0.f;
    #pragma unroll
    for (int i = 0; i < 8; i++) sum += red[i];

    wout[(size_t)row*LK + t] = e * (1.0f / sum);
}

// ---------------------------------------------------------------------------
// attended[b,i,:] = sum_j w[b,i,j] * v[b,j,:]
// Block: 16 q-rows x 128 d-cols, 128 threads, micro 2q x 8d via FFMA2.
// grid (6, 16, B) = 384 blocks.
// ---------------------------------------------------------------------------
__global__ __launch_bounds__(128) void av_kernel(const float* __restrict__ wts,
                                                 float* __restrict__ out)
{
    const int bz = blockIdx.z;
    const int q0 = blockIdx.y * 16;
    const int d0 = blockIdx.x * 128;

    __shared__ float Vs[32][128];     // [j][d]
    __shared__ float Wt[32][18];      // [j][q], EVEN pad -> 8B-aligned float2 rows

    const int t  = threadIdx.x;       // 0..127
    const int tx = t & 15;            // d: 8 floats at tx*8
    const int ty = t >> 4;            // 0..7 -> q rows ty*2, ty*2+1

    unsigned long long acc[2][4];
    #pragma unroll
    for (int i = 0; i < 2; i++)
        #pragma unroll
        for (int p = 0; p < 4; p++) acc[i][p] = 0ull;

    const int vr = t >> 2;            // V row 0..31
    const int vcb = (t & 3) * 32;     // V col base
    const int wq = t & 15;            // W q index 0..15
    const int wj = (t >> 4) * 4;      // W j base 0..28

    for (int j0 = 0; j0 < LK; j0 += 32) {
        const float* vp = g_v + ((size_t)bz*LK + j0 + vr) * DD + d0 + vcb;
        #pragma unroll
        for (int u = 0; u < 8; u++)
            *(float4*)&Vs[vr][vcb + u*4] = *(const float4*)(vp + u*4);
        float4 w4 = *(const float4*)&wts[((size_t)bz*LQ + q0 + wq) * LK + j0 + wj];
        Wt[wj+0][wq] = w4.x; Wt[wj+1][wq] = w4.y;
        Wt[wj+2][wq] = w4.z; Wt[wj+3][wq] = w4.w;
        __syncthreads();

        #pragma unroll
        for (int j = 0; j < 32; j++) {
            ulonglong2 v01 = *(const ulonglong2*)&Vs[j][tx*8];
            ulonglong2 v23 = *(const ulonglong2*)&Vs[j][tx*8 + 4];
            float2 w2 = *(const float2*)&Wt[j][ty*2];
            unsigned long long aa0 = pack2(w2.x, w2.x);
            unsigned long long aa1 = pack2(w2.y, w2.y);
            ffma2(acc[0][0], aa0, v01.x);
            ffma2(acc[0][1], aa0, v01.y);
            ffma2(acc[0][2], aa0, v23.x);
            ffma2(acc[0][3], aa0, v23.y);
            ffma2(acc[1][0], aa1, v01.x);
            ffma2(acc[1][1], aa1, v01.y);
            ffma2(acc[1][2], aa1, v23.x);
            ffma2(acc[1][3], aa1, v23.y);
        }
        __syncthreads();
    }

    #pragma unroll
    for (int i = 0; i < 2; i++) {
        float* op = out + ((size_t)bz*LQ + q0 + ty*2 + i) * DD + d0 + tx*8;
        float2 p0 = unpack2(acc[i][0]);
        float2 p1 = unpack2(acc[i][1]);
        float2 p2 = unpack2(acc[i][2]);
        float2 p3 = unpack2(acc[i][3]);
        float4 r0 = { p0.x, p0.y, p1.x, p1.y };
        float4 r1 = { p2.x, p2.y, p3.x, p3.y };
        *(float4*)(op + 0) = r0;
        *(float4*)(op + 4) = r1;
    }
}

// ---------------------------------------------------------------------------
extern "C" void kernel_launch(void* const* d_in, const int* in_sizes, int n_in,
                              void* d_out, int out_size)
{
    const float* query = (const float*)d_in[0];
    const float* key   = (const float*)d_in[1];
    const float* value = (const float*)d_in[2];
    const float* Wq    = (const float*)d_in[3];
    const float* bq    = (const float*)d_in[4];
    const float* Wk    = (const float*)d_in[5];
    const float* bk    = (const float*)d_in[6];
    const float* Wv    = (const float*)d_in[7];
    const float* bv    = (const float*)d_in[8];
    const float* Ws    = (const float*)d_in[9];
    const float* bs    = (const float*)d_in[10];

    float* att = (float*)d_out;                  // [B,LQ,D]
    float* wts = att + (size_t)BB * LQ * DD;     // [B,LQ,LK]

    proj_kernel<<<dim3(DD/128, (BB*LQ)/128, 3), 256>>>(
        query, key, value, Wq, bq, Wk, bk, Wv, bv);

    score_kernel<<<dim3(LK/32, LQ/32, BB), 256>>>(Ws, bs);

    softmax_kernel<<<BB*LQ, 256>>>(wts);

    av_kernel<<<dim3(DD/128, LQ/16, BB), 128>>>(wts, att);
}